// round 1
// baseline (speedup 1.0000x reference)
#include <cuda_runtime.h>
#include <math.h>

// ---------------------------------------------------------------------------
// Shapes (fixed for this problem)
// ---------------------------------------------------------------------------
constexpr int HN   = 4;     // heads
constexpr int BN   = 2;     // batch
constexpr int CN   = 64;    // in channels
constexpr int TN   = 2048;  // time
constexpr int FN   = 64;    // freqs
constexpr int HIDN = 4;     // q/k channels per head
constexpr int VDN  = 16;    // v channels per head
constexpr int HBN  = HN * BN;        // 8
constexpr int DQK  = HIDN * FN;      // 256
constexpr int DV   = VDN * FN;       // 1024
constexpr float SCALE = 0.0625f;     // 1/sqrt(256)
constexpr float EPS = 1e-5f;

// ---------------------------------------------------------------------------
// Scratch (static device globals; no runtime allocation)
// ---------------------------------------------------------------------------
__device__ float g_Q[(size_t)HBN * TN * DQK];     // (hb, t, o*F+f)      16.8 MB
__device__ float g_K[(size_t)HBN * TN * DQK];     //                     16.8 MB
__device__ float g_V[(size_t)HBN * TN * DV];      // (hb, t, vd*F+f)     67 MB
__device__ float g_S[(size_t)HBN * TN * TN];      // attention scores    134 MB
__device__ float g_O[(size_t)BN * CN * TN * FN];  // (b, h*VD+vd, t, f)  67 MB

// ---------------------------------------------------------------------------
// Kernel 1: fused QKV projection + bias + PReLU + LayerNorm(chan,freq)
// grid (TN, BN), 256 threads. Dynamic smem.
// ---------------------------------------------------------------------------
constexpr int QKV_SMEM_FLOATS = 4096 /*xs*/ + 6144 /*ws*/ + 6144 /*ys*/
                              + 96 + 96 + 12 + 12;
constexpr int QKV_SMEM_BYTES  = QKV_SMEM_FLOATS * 4;

__global__ void __launch_bounds__(256)
qkv_kernel(const float* __restrict__ x,
           const float* __restrict__ Wq, const float* __restrict__ bq,
           const float* __restrict__ aq, const float* __restrict__ gq,
           const float* __restrict__ betq,
           const float* __restrict__ Wk, const float* __restrict__ bk,
           const float* __restrict__ ak, const float* __restrict__ gk,
           const float* __restrict__ betk,
           const float* __restrict__ Wv, const float* __restrict__ bv,
           const float* __restrict__ av, const float* __restrict__ gv,
           const float* __restrict__ betv)
{
    extern __shared__ float sm[];
    float* xs     = sm;            // [64][64]  input tile (c, f)
    float* ws     = sm + 4096;     // [96][64]  stacked weights (row, c)
    float* ys     = sm + 10240;    // [96][64]  prelu'd outputs (row, f)
    float* rowsum = sm + 16384;    // [96]
    float* rowsq  = rowsum + 96;   // [96]
    float* segmu  = rowsq + 96;    // [12]
    float* segrs  = segmu + 12;    // [12]

    const int tid = threadIdx.x;
    const int t   = blockIdx.x;
    const int b   = blockIdx.y;

    // ---- load x tile (c, f) and stacked weights ----
    for (int i = tid; i < 4096; i += 256) {
        int c = i >> 6, f = i & 63;
        xs[i] = x[(((size_t)b * 64 + c) * TN + t) * 64 + f];
    }
    for (int i = tid; i < 6144; i += 256) {
        int r = i >> 6;
        float w;
        if (r < 16)      w = Wq[i];
        else if (r < 32) w = Wk[i - 1024];
        else             w = Wv[i - 2048];
        ws[i] = w;
    }
    __syncthreads();

    // ---- 96x64 = W @ x, bias, prelu ----
    const int f0 = (tid & 15) * 4;
    const int rb = tid >> 4;
    #pragma unroll
    for (int rr = 0; rr < 6; rr++) {
        int r = rb + rr * 16;
        float a0 = 0.f, a1 = 0.f, a2 = 0.f, a3 = 0.f;
        #pragma unroll
        for (int c = 0; c < 64; c++) {
            float w = ws[r * 64 + c];
            float4 xv = *(const float4*)&xs[c * 64 + f0];
            a0 += w * xv.x; a1 += w * xv.y; a2 += w * xv.z; a3 += w * xv.w;
        }
        float bias, slope;
        if (r < 16)      { bias = bq[r];      slope = aq[r >> 2]; }
        else if (r < 32) { bias = bk[r - 16]; slope = ak[(r - 16) >> 2]; }
        else             { bias = bv[r - 32]; slope = av[(r - 32) >> 4]; }
        a0 += bias; a1 += bias; a2 += bias; a3 += bias;
        a0 = a0 >= 0.f ? a0 : slope * a0;
        a1 = a1 >= 0.f ? a1 : slope * a1;
        a2 = a2 >= 0.f ? a2 : slope * a2;
        a3 = a3 >= 0.f ? a3 : slope * a3;
        ys[r * 64 + f0]     = a0;
        ys[r * 64 + f0 + 1] = a1;
        ys[r * 64 + f0 + 2] = a2;
        ys[r * 64 + f0 + 3] = a3;
    }
    __syncthreads();

    // ---- per-row sums (warp w owns rows [12w, 12w+12)) ----
    {
        int wid = tid >> 5, lane = tid & 31;
        for (int i = 0; i < 12; i++) {
            int r = wid * 12 + i;
            float v1 = ys[r * 64 + lane];
            float v2 = ys[r * 64 + lane + 32];
            float s = v1 + v2;
            float q = v1 * v1 + v2 * v2;
            #pragma unroll
            for (int off = 16; off > 0; off >>= 1) {
                s += __shfl_xor_sync(0xffffffffu, s, off);
                q += __shfl_xor_sync(0xffffffffu, q, off);
            }
            if (lane == 0) { rowsum[r] = s; rowsq[r] = q; }
        }
    }
    __syncthreads();

    // ---- segment (per-head) LN stats: 4 Q segs, 4 K segs, 4 V segs ----
    if (tid < 12) {
        int s = tid, r0, nrows; float cnt;
        if (s < 4)      { r0 = s * 4;              nrows = 4;  cnt = 256.f;  }
        else if (s < 8) { r0 = 16 + (s - 4) * 4;   nrows = 4;  cnt = 256.f;  }
        else            { r0 = 32 + (s - 8) * 16;  nrows = 16; cnt = 1024.f; }
        float su = 0.f, sq = 0.f;
        for (int i = 0; i < nrows; i++) { su += rowsum[r0 + i]; sq += rowsq[r0 + i]; }
        float mu = su / cnt;
        float var = sq / cnt - mu * mu;
        segmu[s] = mu;
        segrs[s] = rsqrtf(var + EPS);
    }
    __syncthreads();

    // ---- normalize, affine, scatter to Q/K/V with attention layout ----
    for (int i = 0; i < 24; i++) {
        int idx = tid + i * 256;
        int r = idx >> 6, f = idx & 63;
        int seg;
        if (r < 16)      seg = r >> 2;
        else if (r < 32) seg = 4 + ((r - 16) >> 2);
        else             seg = 8 + ((r - 32) >> 4);
        float val = (ys[idx] - segmu[seg]) * segrs[seg];
        if (r < 16) {
            int h = r >> 2, o = r & 3;
            g_Q[(((size_t)(h * 2 + b)) * TN + t) * DQK + o * 64 + f]
                = val * gq[idx] + betq[idx];
        } else if (r < 32) {
            int rk = r - 16, h = rk >> 2, o = rk & 3, i2 = rk * 64 + f;
            g_K[(((size_t)(h * 2 + b)) * TN + t) * DQK + o * 64 + f]
                = val * gk[i2] + betk[i2];
        } else {
            int rv = r - 32, h = rv >> 4, vd = rv & 15, i2 = rv * 64 + f;
            g_V[(((size_t)(h * 2 + b)) * TN + t) * DV + vd * 64 + f]
                = val * gv[i2] + betv[i2];
        }
    }
}

// ---------------------------------------------------------------------------
// Kernel 2a: S = (Q @ K^T) * scale.  64x64 tiles, 256 threads, 4x4 per thread.
// grid (32 n-tiles, 32 m-tiles, 8 hb)
// ---------------------------------------------------------------------------
__global__ void __launch_bounds__(256)
gemm_qk_kernel()
{
    __shared__ float As[16 * 68];   // [kk][row], padded stride 68
    __shared__ float Bs[16 * 68];

    const int tid = threadIdx.x;
    const int tx = tid & 15, ty = tid >> 4;
    const int bx = blockIdx.x, by = blockIdx.y, hb = blockIdx.z;

    const float* Qb = g_Q + (size_t)hb * TN * DQK;
    const float* Kb = g_K + (size_t)hb * TN * DQK;

    const int arow = tid >> 2, ak = (tid & 3) * 4;

    float acc[4][4] = {};
    for (int k0 = 0; k0 < DQK; k0 += 16) {
        float4 qa = *(const float4*)(Qb + (size_t)(by * 64 + arow) * DQK + k0 + ak);
        float4 kb = *(const float4*)(Kb + (size_t)(bx * 64 + arow) * DQK + k0 + ak);
        As[(ak + 0) * 68 + arow] = qa.x; As[(ak + 1) * 68 + arow] = qa.y;
        As[(ak + 2) * 68 + arow] = qa.z; As[(ak + 3) * 68 + arow] = qa.w;
        Bs[(ak + 0) * 68 + arow] = kb.x; Bs[(ak + 1) * 68 + arow] = kb.y;
        Bs[(ak + 2) * 68 + arow] = kb.z; Bs[(ak + 3) * 68 + arow] = kb.w;
        __syncthreads();
        #pragma unroll
        for (int kk = 0; kk < 16; kk++) {
            float a[4], bb[4];
            *(float4*)a  = *(const float4*)&As[kk * 68 + ty * 4];
            *(float4*)bb = *(const float4*)&Bs[kk * 68 + tx * 4];
            #pragma unroll
            for (int i = 0; i < 4; i++)
                #pragma unroll
                for (int j = 0; j < 4; j++)
                    acc[i][j] += a[i] * bb[j];
        }
        __syncthreads();
    }

    float* Sb = g_S + (size_t)hb * TN * TN;
    #pragma unroll
    for (int i = 0; i < 4; i++) {
        int m = by * 64 + ty * 4 + i;
        float4 o;
        o.x = acc[i][0] * SCALE; o.y = acc[i][1] * SCALE;
        o.z = acc[i][2] * SCALE; o.w = acc[i][3] * SCALE;
        *(float4*)(Sb + (size_t)m * TN + bx * 64 + tx * 4) = o;
    }
}

// ---------------------------------------------------------------------------
// Kernel 2b: in-place row softmax over S. One block per row (16384 rows).
// ---------------------------------------------------------------------------
__global__ void __launch_bounds__(256)
softmax_kernel()
{
    __shared__ float redm[8];
    __shared__ float reds[8];
    const int tid = threadIdx.x;
    const int lane = tid & 31, wid = tid >> 5;
    float* p = g_S + (size_t)blockIdx.x * TN;

    float v[8];
    #pragma unroll
    for (int i = 0; i < 8; i++) v[i] = p[tid + i * 256];

    float m = v[0];
    #pragma unroll
    for (int i = 1; i < 8; i++) m = fmaxf(m, v[i]);
    #pragma unroll
    for (int off = 16; off > 0; off >>= 1)
        m = fmaxf(m, __shfl_xor_sync(0xffffffffu, m, off));
    if (lane == 0) redm[wid] = m;
    __syncthreads();
    m = redm[0];
    #pragma unroll
    for (int i = 1; i < 8; i++) m = fmaxf(m, redm[i]);

    float s = 0.f;
    #pragma unroll
    for (int i = 0; i < 8; i++) { v[i] = __expf(v[i] - m); s += v[i]; }
    #pragma unroll
    for (int off = 16; off > 0; off >>= 1)
        s += __shfl_xor_sync(0xffffffffu, s, off);
    if (lane == 0) reds[wid] = s;
    __syncthreads();
    float tot = 0.f;
    #pragma unroll
    for (int i = 0; i < 8; i++) tot += reds[i];
    float inv = 1.f / tot;
    #pragma unroll
    for (int i = 0; i < 8; i++) p[tid + i * 256] = v[i] * inv;
}

// ---------------------------------------------------------------------------
// Kernel 2c: O = P @ V, stored directly as (b, h*VD+vd, t, f).
// grid (16 n-tiles, 32 m-tiles, 8 hb); each n-tile == one vd.
// ---------------------------------------------------------------------------
__global__ void __launch_bounds__(256)
gemm_pv_kernel()
{
    __shared__ float As[16 * 68];   // [kk][m-row]
    __shared__ float Bs[16 * 68];   // [kk][n-col]

    const int tid = threadIdx.x;
    const int tx = tid & 15, ty = tid >> 4;
    const int bx = blockIdx.x, by = blockIdx.y, hb = blockIdx.z;

    const float* Pb = g_S + (size_t)hb * TN * TN;
    const float* Vb = g_V + (size_t)hb * TN * DV;

    const int arow = tid >> 2, ak = (tid & 3) * 4;
    const int krow = tid >> 4, nc = (tid & 15) * 4;

    float acc[4][4] = {};
    for (int k0 = 0; k0 < TN; k0 += 16) {
        float4 pa = *(const float4*)(Pb + (size_t)(by * 64 + arow) * TN + k0 + ak);
        float4 vb = *(const float4*)(Vb + (size_t)(k0 + krow) * DV + bx * 64 + nc);
        As[(ak + 0) * 68 + arow] = pa.x; As[(ak + 1) * 68 + arow] = pa.y;
        As[(ak + 2) * 68 + arow] = pa.z; As[(ak + 3) * 68 + arow] = pa.w;
        *(float4*)&Bs[krow * 68 + nc] = vb;
        __syncthreads();
        #pragma unroll
        for (int kk = 0; kk < 16; kk++) {
            float a[4], bb[4];
            *(float4*)a  = *(const float4*)&As[kk * 68 + ty * 4];
            *(float4*)bb = *(const float4*)&Bs[kk * 68 + tx * 4];
            #pragma unroll
            for (int i = 0; i < 4; i++)
                #pragma unroll
                for (int j = 0; j < 4; j++)
                    acc[i][j] += a[i] * bb[j];
        }
        __syncthreads();
    }

    const int h = hb >> 1, bb_ = hb & 1;
    const int vd = bx;            // exactly one vd per 64-wide n-tile
    #pragma unroll
    for (int i = 0; i < 4; i++) {
        int tq = by * 64 + ty * 4 + i;
        float4 o;
        o.x = acc[i][0]; o.y = acc[i][1]; o.z = acc[i][2]; o.w = acc[i][3];
        *(float4*)(g_O + (((size_t)(bb_ * 64 + h * 16 + vd)) * TN + tq) * FN + tx * 4) = o;
    }
}

// ---------------------------------------------------------------------------
// Kernel 3: output 1x1 conv + bias + PReLU + LN(chan,freq) + residual.
// grid (TN, BN), 256 threads.
// ---------------------------------------------------------------------------
constexpr int PROJ_SMEM_FLOATS = 4096 * 3 + 16 + 16;
constexpr int PROJ_SMEM_BYTES  = PROJ_SMEM_FLOATS * 4;

__global__ void __launch_bounds__(256)
proj_kernel(const float* __restrict__ x,
            const float* __restrict__ Wp, const float* __restrict__ bp,
            const float* __restrict__ ap, const float* __restrict__ gp,
            const float* __restrict__ betp,
            float* __restrict__ out)
{
    extern __shared__ float sm[];
    float* os  = sm;             // [64][64] attention output tile (c, f)
    float* wps = sm + 4096;      // [64][64] Wp
    float* ys  = sm + 8192;      // [64][64]
    float* red  = sm + 12288;    // [8] sums
    float* redq = sm + 12296;    // [8] sumsq

    const int tid = threadIdx.x;
    const int t = blockIdx.x;
    const int b = blockIdx.y;

    for (int i = tid; i < 4096; i += 256) {
        int c = i >> 6, f = i & 63;
        os[i]  = g_O[(((size_t)b * 64 + c) * TN + t) * 64 + f];
        wps[i] = Wp[i];
    }
    __syncthreads();

    const float slope = ap[0];
    const int f0 = (tid & 15) * 4;
    const int rbse = tid >> 4;
    #pragma unroll
    for (int rr = 0; rr < 4; rr++) {
        int r = rbse + rr * 16;
        float a0 = 0.f, a1 = 0.f, a2 = 0.f, a3 = 0.f;
        #pragma unroll
        for (int c = 0; c < 64; c++) {
            float w = wps[r * 64 + c];
            float4 xv = *(const float4*)&os[c * 64 + f0];
            a0 += w * xv.x; a1 += w * xv.y; a2 += w * xv.z; a3 += w * xv.w;
        }
        float bias = bp[r];
        a0 += bias; a1 += bias; a2 += bias; a3 += bias;
        a0 = a0 >= 0.f ? a0 : slope * a0;
        a1 = a1 >= 0.f ? a1 : slope * a1;
        a2 = a2 >= 0.f ? a2 : slope * a2;
        a3 = a3 >= 0.f ? a3 : slope * a3;
        ys[r * 64 + f0]     = a0;
        ys[r * 64 + f0 + 1] = a1;
        ys[r * 64 + f0 + 2] = a2;
        ys[r * 64 + f0 + 3] = a3;
    }
    __syncthreads();

    // LN over all 64x64 elements
    float s = 0.f, q = 0.f;
    for (int i = 0; i < 16; i++) {
        float v = ys[tid + i * 256];
        s += v; q += v * v;
    }
    const int lane = tid & 31, wid = tid >> 5;
    #pragma unroll
    for (int off = 16; off > 0; off >>= 1) {
        s += __shfl_xor_sync(0xffffffffu, s, off);
        q += __shfl_xor_sync(0xffffffffu, q, off);
    }
    if (lane == 0) { red[wid] = s; redq[wid] = q; }
    __syncthreads();
    float su = 0.f, sq = 0.f;
    #pragma unroll
    for (int i = 0; i < 8; i++) { su += red[i]; sq += redq[i]; }
    float mu = su * (1.f / 4096.f);
    float var = sq * (1.f / 4096.f) - mu * mu;
    float rs = rsqrtf(var + EPS);

    for (int i = 0; i < 16; i++) {
        int idx = tid + i * 256;
        int r = idx >> 6, f = idx & 63;
        size_t gidx = (((size_t)b * 64 + r) * TN + t) * 64 + f;
        out[gidx] = (ys[idx] - mu) * rs * gp[idx] + betp[idx] + x[gidx];
    }
}

// ---------------------------------------------------------------------------
// Launch
// ---------------------------------------------------------------------------
extern "C" void kernel_launch(void* const* d_in, const int* in_sizes, int n_in,
                              void* d_out, int out_size)
{
    const float* x    = (const float*)d_in[0];
    const float* Wq   = (const float*)d_in[1];
    const float* bq   = (const float*)d_in[2];
    const float* aq   = (const float*)d_in[3];
    const float* gq   = (const float*)d_in[4];
    const float* betq = (const float*)d_in[5];
    const float* Wk   = (const float*)d_in[6];
    const float* bk   = (const float*)d_in[7];
    const float* ak   = (const float*)d_in[8];
    const float* gk   = (const float*)d_in[9];
    const float* betk = (const float*)d_in[10];
    const float* Wv   = (const float*)d_in[11];
    const float* bv   = (const float*)d_in[12];
    const float* av   = (const float*)d_in[13];
    const float* gv   = (const float*)d_in[14];
    const float* betv = (const float*)d_in[15];
    const float* Wp   = (const float*)d_in[16];
    const float* bp   = (const float*)d_in[17];
    const float* ap   = (const float*)d_in[18];
    const float* gp   = (const float*)d_in[19];
    const float* betp = (const float*)d_in[20];
    float* out = (float*)d_out;

    cudaFuncSetAttribute(qkv_kernel, cudaFuncAttributeMaxDynamicSharedMemorySize,
                         QKV_SMEM_BYTES);
    cudaFuncSetAttribute(proj_kernel, cudaFuncAttributeMaxDynamicSharedMemorySize,
                         PROJ_SMEM_BYTES);

    qkv_kernel<<<dim3(TN, BN), 256, QKV_SMEM_BYTES>>>(
        x, Wq, bq, aq, gq, betq, Wk, bk, ak, gk, betk, Wv, bv, av, gv, betv);

    gemm_qk_kernel<<<dim3(TN / 64, TN / 64, HBN), 256>>>();

    softmax_kernel<<<HBN * TN, 256>>>();

    gemm_pv_kernel<<<dim3(DV / 64, TN / 64, HBN), 256>>>();

    proj_kernel<<<dim3(TN, BN), 256, PROJ_SMEM_BYTES>>>(
        x, Wp, bp, ap, gp, betp, out);
}

// round 5
// speedup vs baseline: 1.7841x; 1.7841x over previous
#include <cuda_runtime.h>
#include <cuda_bf16.h>
#include <cstdint>
#include <math.h>

// ---------------------------------------------------------------------------
// Shapes
// ---------------------------------------------------------------------------
constexpr int HN   = 4;
constexpr int BN   = 2;
constexpr int CN   = 64;
constexpr int TN   = 2048;
constexpr int FN   = 64;
constexpr int HIDN = 4;
constexpr int VDN  = 16;
constexpr int HBN  = HN * BN;        // 8
constexpr int DQK  = HIDN * FN;      // 256
constexpr int DV   = VDN * FN;       // 1024
constexpr float SCALE = 0.0625f;     // 1/sqrt(256), folded into Q
constexpr float EPS = 1e-5f;

// ---------------------------------------------------------------------------
// Scratch (static device globals)
// ---------------------------------------------------------------------------
__device__ __nv_bfloat16 g_Qhi[(size_t)HBN * TN * DQK];
__device__ __nv_bfloat16 g_Qlo[(size_t)HBN * TN * DQK];
__device__ __nv_bfloat16 g_Khi[(size_t)HBN * TN * DQK];
__device__ __nv_bfloat16 g_Klo[(size_t)HBN * TN * DQK];
__device__ __nv_bfloat16 g_Vhi[(size_t)HBN * TN * DV];     // [hb, t, d]
__device__ __nv_bfloat16 g_Vlo[(size_t)HBN * TN * DV];
__device__ __nv_bfloat16 g_VThi[(size_t)HBN * DV * TN];    // [hb, d, t]
__device__ __nv_bfloat16 g_VTlo[(size_t)HBN * DV * TN];
__device__ float         g_S[(size_t)HBN * TN * TN];       // raw scores (scaled)
__device__ __nv_bfloat16 g_Phi[(size_t)HBN * TN * TN];     // softmax probs hi
__device__ __nv_bfloat16 g_Plo[(size_t)HBN * TN * TN];     // softmax probs lo
__device__ float         g_O[(size_t)BN * CN * TN * FN];   // (b, h*VD+vd, t, f)

// ---------------------------------------------------------------------------
// Portable tensor-core helpers (sm_80 ISA; works on plain sm_100 target)
// ---------------------------------------------------------------------------
__device__ __forceinline__ uint32_t smem_to_u32(const void* p) {
    uint32_t a;
    asm("{ .reg .u64 t; cvta.to.shared.u64 t, %1; cvt.u32.u64 %0, t; }"
        : "=r"(a) : "l"(p));
    return a;
}

__device__ __forceinline__ void ldsm_x4(uint32_t addr, uint32_t& r0, uint32_t& r1,
                                        uint32_t& r2, uint32_t& r3) {
    asm volatile("ldmatrix.sync.aligned.m8n8.x4.shared.b16 {%0,%1,%2,%3}, [%4];"
        : "=r"(r0), "=r"(r1), "=r"(r2), "=r"(r3) : "r"(addr));
}

__device__ __forceinline__ void mma_bf16(float* c, const uint32_t* a, const uint32_t* b) {
    asm volatile(
        "mma.sync.aligned.m16n8k16.row.col.f32.bf16.bf16.f32 "
        "{%0,%1,%2,%3}, {%4,%5,%6,%7}, {%8,%9}, {%0,%1,%2,%3};"
        : "+f"(c[0]), "+f"(c[1]), "+f"(c[2]), "+f"(c[3])
        : "r"(a[0]), "r"(a[1]), "r"(a[2]), "r"(a[3]), "r"(b[0]), "r"(b[1]));
}

__device__ __forceinline__ void split_bf16(float v, __nv_bfloat16& h, __nv_bfloat16& l) {
    h = __float2bfloat16_rn(v);
    l = __float2bfloat16_rn(v - __bfloat162float(h));
}

// ---------------------------------------------------------------------------
// Kernel 1: fused QKV projection + bias + PReLU + LN; emits bf16 hi/lo splits
// grid (TN, BN), 256 threads.
// ---------------------------------------------------------------------------
constexpr int QKV_SMEM_FLOATS = 4096 + 6144 + 6144 + 96 + 96 + 12 + 12;
constexpr int QKV_SMEM_BYTES  = QKV_SMEM_FLOATS * 4;

__global__ void __launch_bounds__(256)
qkv_kernel(const float* __restrict__ x,
           const float* __restrict__ Wq, const float* __restrict__ bq,
           const float* __restrict__ aq, const float* __restrict__ gq,
           const float* __restrict__ betq,
           const float* __restrict__ Wk, const float* __restrict__ bk,
           const float* __restrict__ ak, const float* __restrict__ gk,
           const float* __restrict__ betk,
           const float* __restrict__ Wv, const float* __restrict__ bv,
           const float* __restrict__ av, const float* __restrict__ gv,
           const float* __restrict__ betv)
{
    extern __shared__ float sm[];
    float* xs     = sm;
    float* ws     = sm + 4096;
    float* ys     = sm + 10240;
    float* rowsum = sm + 16384;
    float* rowsq  = rowsum + 96;
    float* segmu  = rowsq + 96;
    float* segrs  = segmu + 12;

    const int tid = threadIdx.x;
    const int t   = blockIdx.x;
    const int b   = blockIdx.y;

    for (int i = tid; i < 4096; i += 256) {
        int c = i >> 6, f = i & 63;
        xs[i] = x[(((size_t)b * 64 + c) * TN + t) * 64 + f];
    }
    for (int i = tid; i < 6144; i += 256) {
        int r = i >> 6;
        float w;
        if (r < 16)      w = Wq[i];
        else if (r < 32) w = Wk[i - 1024];
        else             w = Wv[i - 2048];
        ws[i] = w;
    }
    __syncthreads();

    const int f0 = (tid & 15) * 4;
    const int rb = tid >> 4;
    #pragma unroll
    for (int rr = 0; rr < 6; rr++) {
        int r = rb + rr * 16;
        float a0 = 0.f, a1 = 0.f, a2 = 0.f, a3 = 0.f;
        #pragma unroll
        for (int c = 0; c < 64; c++) {
            float w = ws[r * 64 + c];
            float4 xv = *(const float4*)&xs[c * 64 + f0];
            a0 += w * xv.x; a1 += w * xv.y; a2 += w * xv.z; a3 += w * xv.w;
        }
        float bias, slope;
        if (r < 16)      { bias = bq[r];      slope = aq[r >> 2]; }
        else if (r < 32) { bias = bk[r - 16]; slope = ak[(r - 16) >> 2]; }
        else             { bias = bv[r - 32]; slope = av[(r - 32) >> 4]; }
        a0 += bias; a1 += bias; a2 += bias; a3 += bias;
        a0 = a0 >= 0.f ? a0 : slope * a0;
        a1 = a1 >= 0.f ? a1 : slope * a1;
        a2 = a2 >= 0.f ? a2 : slope * a2;
        a3 = a3 >= 0.f ? a3 : slope * a3;
        ys[r * 64 + f0]     = a0;
        ys[r * 64 + f0 + 1] = a1;
        ys[r * 64 + f0 + 2] = a2;
        ys[r * 64 + f0 + 3] = a3;
    }
    __syncthreads();

    {
        int wid = tid >> 5, lane = tid & 31;
        for (int i = 0; i < 12; i++) {
            int r = wid * 12 + i;
            float v1 = ys[r * 64 + lane];
            float v2 = ys[r * 64 + lane + 32];
            float s = v1 + v2;
            float q = v1 * v1 + v2 * v2;
            #pragma unroll
            for (int off = 16; off > 0; off >>= 1) {
                s += __shfl_xor_sync(0xffffffffu, s, off);
                q += __shfl_xor_sync(0xffffffffu, q, off);
            }
            if (lane == 0) { rowsum[r] = s; rowsq[r] = q; }
        }
    }
    __syncthreads();

    if (tid < 12) {
        int s = tid, r0, nrows; float cnt;
        if (s < 4)      { r0 = s * 4;              nrows = 4;  cnt = 256.f;  }
        else if (s < 8) { r0 = 16 + (s - 4) * 4;   nrows = 4;  cnt = 256.f;  }
        else            { r0 = 32 + (s - 8) * 16;  nrows = 16; cnt = 1024.f; }
        float su = 0.f, sq = 0.f;
        for (int i = 0; i < nrows; i++) { su += rowsum[r0 + i]; sq += rowsq[r0 + i]; }
        float mu = su / cnt;
        float var = sq / cnt - mu * mu;
        segmu[s] = mu;
        segrs[s] = rsqrtf(var + EPS);
    }
    __syncthreads();

    for (int i = 0; i < 24; i++) {
        int idx = tid + i * 256;
        int r = idx >> 6, f = idx & 63;
        int seg;
        if (r < 16)      seg = r >> 2;
        else if (r < 32) seg = 4 + ((r - 16) >> 2);
        else             seg = 8 + ((r - 32) >> 4);
        float val = (ys[idx] - segmu[seg]) * segrs[seg];
        __nv_bfloat16 hi, lo;
        if (r < 16) {
            int h = r >> 2, o = r & 3;
            float q = (val * gq[idx] + betq[idx]) * SCALE;   // fold attention scale
            split_bf16(q, hi, lo);
            size_t gi = (((size_t)(h * 2 + b)) * TN + t) * DQK + o * 64 + f;
            g_Qhi[gi] = hi; g_Qlo[gi] = lo;
        } else if (r < 32) {
            int rk = r - 16, h = rk >> 2, o = rk & 3, i2 = rk * 64 + f;
            float k = val * gk[i2] + betk[i2];
            split_bf16(k, hi, lo);
            size_t gi = (((size_t)(h * 2 + b)) * TN + t) * DQK + o * 64 + f;
            g_Khi[gi] = hi; g_Klo[gi] = lo;
        } else {
            int rv = r - 32, h = rv >> 4, vd = rv & 15, i2 = rv * 64 + f;
            float v = val * gv[i2] + betv[i2];
            split_bf16(v, hi, lo);
            size_t gi = (((size_t)(h * 2 + b)) * TN + t) * DV + vd * 64 + f;
            g_Vhi[gi] = hi; g_Vlo[gi] = lo;
        }
    }
}

// ---------------------------------------------------------------------------
// Kernel 1b: transpose V [hb, t, d] -> VT [hb, d, t], 32x32 tiles
// ---------------------------------------------------------------------------
__global__ void __launch_bounds__(256)
transpose_v_kernel()
{
    __shared__ __nv_bfloat16 th[32][33];
    __shared__ __nv_bfloat16 tl[32][33];
    const int tx = threadIdx.x, ty = threadIdx.y;
    const int d0 = blockIdx.x * 32, t0 = blockIdx.y * 32, hb = blockIdx.z;

    const __nv_bfloat16* src_h = g_Vhi + (size_t)hb * TN * DV;
    const __nv_bfloat16* src_l = g_Vlo + (size_t)hb * TN * DV;
    #pragma unroll
    for (int j = 0; j < 4; j++) {
        int row = ty + j * 8;
        th[row][tx] = src_h[(size_t)(t0 + row) * DV + d0 + tx];
        tl[row][tx] = src_l[(size_t)(t0 + row) * DV + d0 + tx];
    }
    __syncthreads();
    __nv_bfloat16* dst_h = g_VThi + (size_t)hb * DV * TN;
    __nv_bfloat16* dst_l = g_VTlo + (size_t)hb * DV * TN;
    #pragma unroll
    for (int j = 0; j < 4; j++) {
        int row = ty + j * 8;
        dst_h[(size_t)(d0 + row) * TN + t0 + tx] = th[tx][row];
        dst_l[(size_t)(d0 + row) * TN + t0 + tx] = tl[tx][row];
    }
}

// ---------------------------------------------------------------------------
// mma.sync split-bf16 GEMM core.
// CTA tile 128x128, K-chunk 64.  8 warps, warp tile 32(m) x 64(n).
// A, B both K-contiguous (row.col mma).  3 passes: Ah*Bh + Al*Bh + Ah*Bl.
// smem: 4 tiles of [128][72] bf16 (stride 72 elems = 144B, ldmatrix
// conflict-free since 144 = 9*16B).
// ---------------------------------------------------------------------------
constexpr int KC = 64;
constexpr int SPITCH = 72;                       // bf16 elements
constexpr int TILE_ELEMS = 128 * SPITCH;         // 9216
constexpr int TILE_BYTES = TILE_ELEMS * 2;       // 18432
constexpr int GEMM_SMEM_BYTES = 4 * TILE_BYTES;  // 73728

template <int PITCH, int NCHUNK>
__device__ __forceinline__ void gemm_split_mainloop(
    __nv_bfloat16* smb, int tid, int wid, int lane,
    const __nv_bfloat16* __restrict__ Ah, const __nv_bfloat16* __restrict__ Al,
    const __nv_bfloat16* __restrict__ Bh, const __nv_bfloat16* __restrict__ Bl,
    float acc[2][8][4])
{
    __nv_bfloat16* sAh = smb;
    __nv_bfloat16* sAl = smb + TILE_ELEMS;
    __nv_bfloat16* sBh = smb + 2 * TILE_ELEMS;
    __nv_bfloat16* sBl = smb + 3 * TILE_ELEMS;
    const uint32_t base = smem_to_u32(smb);
    const int wm = wid >> 1, wn = wid & 1;

    // ldmatrix per-lane offsets (element units)
    const int a_row = lane & 15;
    const int a_kh  = (lane >> 4) * 8;
    const int b_n   = ((lane >> 4) * 8) + (lane & 7);
    const int b_kh  = ((lane >> 3) & 1) * 8;

    for (int c = 0; c < NCHUNK; c++) {
        const int k0 = c * KC;
        for (int i = tid; i < 1024; i += 256) {
            int r = i >> 3, u = i & 7;
            int so = r * SPITCH + u * 8;
            size_t go = (size_t)r * PITCH + k0 + u * 8;
            *(uint4*)(sAh + so) = *(const uint4*)(Ah + go);
            *(uint4*)(sAl + so) = *(const uint4*)(Al + go);
            *(uint4*)(sBh + so) = *(const uint4*)(Bh + go);
            *(uint4*)(sBl + so) = *(const uint4*)(Bl + go);
        }
        __syncthreads();

        #pragma unroll
        for (int kk = 0; kk < 4; kk++) {
            uint32_t ah[2][4], al[2][4], bh[4][4], bl[4][4];
            #pragma unroll
            for (int i = 0; i < 2; i++) {
                int eo = (wm * 32 + i * 16 + a_row) * SPITCH + kk * 16 + a_kh;
                ldsm_x4(base + 0 * TILE_BYTES + eo * 2,
                        ah[i][0], ah[i][1], ah[i][2], ah[i][3]);
                ldsm_x4(base + 1 * TILE_BYTES + eo * 2,
                        al[i][0], al[i][1], al[i][2], al[i][3]);
            }
            #pragma unroll
            for (int jp = 0; jp < 4; jp++) {
                int eo = (wn * 64 + jp * 16 + b_n) * SPITCH + kk * 16 + b_kh;
                ldsm_x4(base + 2 * TILE_BYTES + eo * 2,
                        bh[jp][0], bh[jp][1], bh[jp][2], bh[jp][3]);
                ldsm_x4(base + 3 * TILE_BYTES + eo * 2,
                        bl[jp][0], bl[jp][1], bl[jp][2], bl[jp][3]);
            }
            #pragma unroll
            for (int i = 0; i < 2; i++) {
                #pragma unroll
                for (int jp = 0; jp < 4; jp++) {
                    mma_bf16(acc[i][2 * jp],     ah[i], &bh[jp][0]);
                    mma_bf16(acc[i][2 * jp],     al[i], &bh[jp][0]);
                    mma_bf16(acc[i][2 * jp],     ah[i], &bl[jp][0]);
                    mma_bf16(acc[i][2 * jp + 1], ah[i], &bh[jp][2]);
                    mma_bf16(acc[i][2 * jp + 1], al[i], &bh[jp][2]);
                    mma_bf16(acc[i][2 * jp + 1], ah[i], &bl[jp][2]);
                }
            }
        }
        __syncthreads();
    }
}

// S = Q @ K^T (scale pre-folded).  grid (TN/128, TN/128, HBN)
__global__ void __launch_bounds__(256)
mma_qk_kernel()
{
    extern __shared__ __align__(16) __nv_bfloat16 smb[];
    const int tid = threadIdx.x, wid = tid >> 5, lane = tid & 31;
    const int bx = blockIdx.x, by = blockIdx.y, hb = blockIdx.z;

    float acc[2][8][4] = {};
    const size_t qb = (size_t)hb * TN * DQK + (size_t)(by * 128) * DQK;
    const size_t kb = (size_t)hb * TN * DQK + (size_t)(bx * 128) * DQK;
    gemm_split_mainloop<DQK, DQK / KC>(smb, tid, wid, lane,
        g_Qhi + qb, g_Qlo + qb, g_Khi + kb, g_Klo + kb, acc);

    const int wm = wid >> 1, wn = wid & 1;
    const int r = lane >> 2, cc = (lane & 3) * 2;
    float* Sb = g_S + (size_t)hb * TN * TN;
    #pragma unroll
    for (int i = 0; i < 2; i++) {
        int m0 = by * 128 + wm * 32 + i * 16 + r;
        #pragma unroll
        for (int j = 0; j < 8; j++) {
            int n = bx * 128 + wn * 64 + j * 8 + cc;
            *(float2*)&Sb[(size_t)m0 * TN + n]       = make_float2(acc[i][j][0], acc[i][j][1]);
            *(float2*)&Sb[(size_t)(m0 + 8) * TN + n] = make_float2(acc[i][j][2], acc[i][j][3]);
        }
    }
}

// O = P @ V.  grid (DV/128, TN/128, HBN)
__global__ void __launch_bounds__(256)
mma_pv_kernel()
{
    extern __shared__ __align__(16) __nv_bfloat16 smb[];
    const int tid = threadIdx.x, wid = tid >> 5, lane = tid & 31;
    const int bx = blockIdx.x, by = blockIdx.y, hb = blockIdx.z;

    float acc[2][8][4] = {};
    const size_t pb = (size_t)hb * TN * TN + (size_t)(by * 128) * TN;
    const size_t vb = (size_t)hb * DV * TN + (size_t)(bx * 128) * TN;
    gemm_split_mainloop<TN, TN / KC>(smb, tid, wid, lane,
        g_Phi + pb, g_Plo + pb, g_VThi + vb, g_VTlo + vb, acc);

    const int wm = wid >> 1, wn = wid & 1;
    const int r = lane >> 2, cc = (lane & 3) * 2;
    const int b_ = hb & 1, h = hb >> 1;
    #pragma unroll
    for (int i = 0; i < 2; i++) {
        int t0 = by * 128 + wm * 32 + i * 16 + r;
        #pragma unroll
        for (int j = 0; j < 8; j++) {
            int d = bx * 128 + wn * 64 + j * 8 + cc;
            int vd = d >> 6, f = d & 63;
            size_t ch = (size_t)(b_ * 64 + h * 16 + vd);
            *(float2*)&g_O[(ch * TN + t0) * 64 + f]     = make_float2(acc[i][j][0], acc[i][j][1]);
            *(float2*)&g_O[(ch * TN + t0 + 8) * 64 + f] = make_float2(acc[i][j][2], acc[i][j][3]);
        }
    }
}

// ---------------------------------------------------------------------------
// Kernel 2b: softmax over S rows -> bf16 hi/lo probs.  FFMA-pipe exp.
// ---------------------------------------------------------------------------
__device__ __forceinline__ float fast_exp(float x) {
    float z = fmaxf(x * 1.44269504088896341f, -80.f);
    int   n = __float2int_rn(z);
    float r = z - (float)n;
    float t = r * 0.693147180559945309f;
    float p = fmaf(t, 1.f / 120.f, 1.f / 24.f);
    p = fmaf(t, p, 1.f / 6.f);
    p = fmaf(t, p, 0.5f);
    p = fmaf(t, p, 1.0f);
    p = fmaf(t, p, 1.0f);
    return p * __int_as_float((n + 127) << 23);
}

__global__ void __launch_bounds__(256)
softmax_kernel()
{
    __shared__ float redm[8];
    __shared__ float reds[8];
    const int tid = threadIdx.x;
    const int lane = tid & 31, wid = tid >> 5;
    const size_t row = blockIdx.x;
    const float* p = g_S + row * TN;

    float v[8];
    #pragma unroll
    for (int i = 0; i < 8; i++) v[i] = p[tid + i * 256];

    float m = v[0];
    #pragma unroll
    for (int i = 1; i < 8; i++) m = fmaxf(m, v[i]);
    #pragma unroll
    for (int off = 16; off > 0; off >>= 1)
        m = fmaxf(m, __shfl_xor_sync(0xffffffffu, m, off));
    if (lane == 0) redm[wid] = m;
    __syncthreads();
    m = redm[0];
    #pragma unroll
    for (int i = 1; i < 8; i++) m = fmaxf(m, redm[i]);

    float s = 0.f;
    #pragma unroll
    for (int i = 0; i < 8; i++) { v[i] = fast_exp(v[i] - m); s += v[i]; }
    #pragma unroll
    for (int off = 16; off > 0; off >>= 1)
        s += __shfl_xor_sync(0xffffffffu, s, off);
    if (lane == 0) reds[wid] = s;
    __syncthreads();
    float tot = 0.f;
    #pragma unroll
    for (int i = 0; i < 8; i++) tot += reds[i];
    float inv = 1.f / tot;

    __nv_bfloat16* ph = g_Phi + row * TN;
    __nv_bfloat16* pl = g_Plo + row * TN;
    #pragma unroll
    for (int i = 0; i < 8; i++) {
        float w = v[i] * inv;
        __nv_bfloat16 hi, lo;
        split_bf16(w, hi, lo);
        ph[tid + i * 256] = hi;
        pl[tid + i * 256] = lo;
    }
}

// ---------------------------------------------------------------------------
// Kernel 3: output projection + PReLU + LN + residual
// ---------------------------------------------------------------------------
constexpr int PROJ_SMEM_FLOATS = 4096 * 3 + 16 + 16;
constexpr int PROJ_SMEM_BYTES  = PROJ_SMEM_FLOATS * 4;

__global__ void __launch_bounds__(256)
proj_kernel(const float* __restrict__ x,
            const float* __restrict__ Wp, const float* __restrict__ bp,
            const float* __restrict__ ap, const float* __restrict__ gp,
            const float* __restrict__ betp,
            float* __restrict__ out)
{
    extern __shared__ float sm[];
    float* os  = sm;
    float* wps = sm + 4096;
    float* ys  = sm + 8192;
    float* red  = sm + 12288;
    float* redq = sm + 12296;

    const int tid = threadIdx.x;
    const int t = blockIdx.x;
    const int b = blockIdx.y;

    for (int i = tid; i < 4096; i += 256) {
        int c = i >> 6, f = i & 63;
        os[i]  = g_O[(((size_t)b * 64 + c) * TN + t) * 64 + f];
        wps[i] = Wp[i];
    }
    __syncthreads();

    const float slope = ap[0];
    const int f0 = (tid & 15) * 4;
    const int rbse = tid >> 4;
    #pragma unroll
    for (int rr = 0; rr < 4; rr++) {
        int r = rbse + rr * 16;
        float a0 = 0.f, a1 = 0.f, a2 = 0.f, a3 = 0.f;
        #pragma unroll
        for (int c = 0; c < 64; c++) {
            float w = wps[r * 64 + c];
            float4 xv = *(const float4*)&os[c * 64 + f0];
            a0 += w * xv.x; a1 += w * xv.y; a2 += w * xv.z; a3 += w * xv.w;
        }
        float bias = bp[r];
        a0 += bias; a1 += bias; a2 += bias; a3 += bias;
        a0 = a0 >= 0.f ? a0 : slope * a0;
        a1 = a1 >= 0.f ? a1 : slope * a1;
        a2 = a2 >= 0.f ? a2 : slope * a2;
        a3 = a3 >= 0.f ? a3 : slope * a3;
        ys[r * 64 + f0]     = a0;
        ys[r * 64 + f0 + 1] = a1;
        ys[r * 64 + f0 + 2] = a2;
        ys[r * 64 + f0 + 3] = a3;
    }
    __syncthreads();

    float s = 0.f, q = 0.f;
    for (int i = 0; i < 16; i++) {
        float v = ys[tid + i * 256];
        s += v; q += v * v;
    }
    const int lane = tid & 31, wid = tid >> 5;
    #pragma unroll
    for (int off = 16; off > 0; off >>= 1) {
        s += __shfl_xor_sync(0xffffffffu, s, off);
        q += __shfl_xor_sync(0xffffffffu, q, off);
    }
    if (lane == 0) { red[wid] = s; redq[wid] = q; }
    __syncthreads();
    float su = 0.f, sq = 0.f;
    #pragma unroll
    for (int i = 0; i < 8; i++) { su += red[i]; sq += redq[i]; }
    float mu = su * (1.f / 4096.f);
    float var = sq * (1.f / 4096.f) - mu * mu;
    float rs = rsqrtf(var + EPS);

    for (int i = 0; i < 16; i++) {
        int idx = tid + i * 256;
        int r = idx >> 6, f = idx & 63;
        size_t gidx = (((size_t)b * 64 + r) * TN + t) * 64 + f;
        out[gidx] = (ys[idx] - mu) * rs * gp[idx] + betp[idx] + x[gidx];
    }
}

// ---------------------------------------------------------------------------
// Launch
// ---------------------------------------------------------------------------
extern "C" void kernel_launch(void* const* d_in, const int* in_sizes, int n_in,
                              void* d_out, int out_size)
{
    const float* x    = (const float*)d_in[0];
    const float* Wq   = (const float*)d_in[1];
    const float* bq   = (const float*)d_in[2];
    const float* aq   = (const float*)d_in[3];
    const float* gq   = (const float*)d_in[4];
    const float* betq = (const float*)d_in[5];
    const float* Wk   = (const float*)d_in[6];
    const float* bk   = (const float*)d_in[7];
    const float* ak   = (const float*)d_in[8];
    const float* gk   = (const float*)d_in[9];
    const float* betk = (const float*)d_in[10];
    const float* Wv   = (const float*)d_in[11];
    const float* bv   = (const float*)d_in[12];
    const float* av   = (const float*)d_in[13];
    const float* gv   = (const float*)d_in[14];
    const float* betv = (const float*)d_in[15];
    const float* Wp   = (const float*)d_in[16];
    const float* bp   = (const float*)d_in[17];
    const float* ap   = (const float*)d_in[18];
    const float* gp   = (const float*)d_in[19];
    const float* betp = (const float*)d_in[20];
    float* out = (float*)d_out;

    cudaFuncSetAttribute(qkv_kernel, cudaFuncAttributeMaxDynamicSharedMemorySize,
                         QKV_SMEM_BYTES);
    cudaFuncSetAttribute(proj_kernel, cudaFuncAttributeMaxDynamicSharedMemorySize,
                         PROJ_SMEM_BYTES);
    cudaFuncSetAttribute(mma_qk_kernel, cudaFuncAttributeMaxDynamicSharedMemorySize,
                         GEMM_SMEM_BYTES);
    cudaFuncSetAttribute(mma_pv_kernel, cudaFuncAttributeMaxDynamicSharedMemorySize,
                         GEMM_SMEM_BYTES);

    qkv_kernel<<<dim3(TN, BN), 256, QKV_SMEM_BYTES>>>(
        x, Wq, bq, aq, gq, betq, Wk, bk, ak, gk, betk, Wv, bv, av, gv, betv);

    transpose_v_kernel<<<dim3(DV / 32, TN / 32, HBN), dim3(32, 8)>>>();

    mma_qk_kernel<<<dim3(TN / 128, TN / 128, HBN), 256, GEMM_SMEM_BYTES>>>();

    softmax_kernel<<<HBN * TN, 256>>>();

    mma_pv_kernel<<<dim3(DV / 128, TN / 128, HBN), 256, GEMM_SMEM_BYTES>>>();

    proj_kernel<<<dim3(TN, BN), 256, PROJ_SMEM_BYTES>>>(
        x, Wp, bp, ap, gp, betp, out);
}